// round 9
// baseline (speedup 1.0000x reference)
#include <cuda_runtime.h>

// Problem dims
#define ZD 96
#define YD 96
#define XD 96
#define PL 9216
#define VOL 884736
#define CH 4
#define KW 7

// Padded x-layout for intermediates
#define XP 104
#define XOFF 4
#define PLP (YD * XP)          // 9984
#define VOLP (ZD * PLP)        // 958464

// Segment configs
#define SEG1 6
#define NSEG1 16
#define SEG2 8
#define NSEG2 12
#define SEG3 6
#define NSEG3 16
#define SEG4 6
#define NSEG4 16

// ---------------- persistent device scratch ----------------
__device__ float g_wlif[CH][KW];
__device__ float g_wq[CH][KW];
__device__ float g_slif[CH][ZD];
__device__ float g_sq[CH][ZD];
__device__ int   g_same;
__device__ float g_u[CH * VOL];
// interleaved pair buffers: element e -> floats [2e]=s0, [2e+1]=s1
__device__ float g_pA[CH * VOLP * 2];   // q1 out (uI,u)z ; q3 out (E,D)
__device__ float g_pB[CH * VOLP * 2];   // q2 out (Cn,Cn2)
__device__ float g_q[CH * VOLP];        // wq z-conv(u) (q1, !same) / full C2q (q2)

// ---------------- zero the x-pad halos ----------------
__global__ void k_zeropad() {
    long nrows = (long)CH * ZD * YD;
    long idx = (long)blockIdx.x * blockDim.x + threadIdx.x;
    long total = nrows * 8;
    if (idx >= total) return;
    long row = idx >> 3;
    int p = (int)(idx & 7);
    int xo = (p < 4) ? p : (XOFF + XD + p - 4);
    long e = row * XP + xo;
    g_pA[2 * e] = 0.f; g_pA[2 * e + 1] = 0.f;
    g_pB[2 * e] = 0.f; g_pB[2 * e + 1] = 0.f;
    g_q[e] = 0.f;
}

// ---------------- setup ----------------
__global__ void k_setup(const float* __restrict__ sigma2,
                        const float* __restrict__ sigma3) {
    int c = threadIdx.x;
    if (c == 0) {
        int s = 1;
        for (int k = 0; k < CH; k++) s &= (sigma2[k] == sigma3[k]);
        g_same = s;
    }
    if (c < CH) {
        float s2 = sigma2[c], s3 = sigma3[c];
        float w2[KW], w3[KW];
        float sum2 = 0.f, sum3 = 0.f;
        for (int t = 0; t < KW; t++) {
            float d = (float)(t - 3);
            w2[t] = expf(-d * d / (2.f * s2 * s2)); sum2 += w2[t];
            w3[t] = expf(-d * d / (2.f * s3 * s3)); sum3 += w3[t];
        }
        for (int t = 0; t < KW; t++) {
            g_wq[c][t]   = w2[t] / sum2;
            g_wlif[c][t] = w3[t] / sum3;
        }
        for (int p = 0; p < ZD; p++) {
            float sl = 0.f, sq = 0.f;
            for (int t = 0; t < KW; t++) {
                int q = p + t - 3;
                if (q >= 0 && q < ZD) { sl += g_wlif[c][t]; sq += g_wq[c][t]; }
            }
            g_slif[c][p] = sl;
            g_sq[c][p]   = sq;
        }
    }
}

// ---------------- u0 = softmax(o / eta) ----------------
__global__ void k_init(const float* __restrict__ o,
                       const float* __restrict__ eta_p) {
    int i = blockIdx.x * blockDim.x + threadIdx.x;
    if (i >= VOL) return;
    float inv_eta = 1.f / eta_p[0];
    float a0 = o[i] * inv_eta;
    float a1 = o[VOL + i] * inv_eta;
    float a2 = o[2 * VOL + i] * inv_eta;
    float a3 = o[3 * VOL + i] * inv_eta;
    float m = fmaxf(fmaxf(a0, a1), fmaxf(a2, a3));
    float e0 = expf(a0 - m), e1 = expf(a1 - m), e2 = expf(a2 - m), e3 = expf(a3 - m);
    float inv = 1.f / (e0 + e1 + e2 + e3);
    g_u[i] = e0 * inv;
    g_u[VOL + i] = e1 * inv;
    g_u[2 * VOL + i] = e2 * inv;
    g_u[3 * VOL + i] = e3 * inv;
}

__device__ __forceinline__ void f2fma(float w, float2 v, float2& acc) {
    acc.x += w * v.x; acc.y += w * v.y;
}
__device__ __forceinline__ void f4fma(float w, float4 v, float4& acc) {
    acc.x += w * v.x; acc.y += w * v.y; acc.z += w * v.z; acc.w += w * v.w;
}

// ============ q1: z-ring conv of {u*I, u} -> interleaved pair out ============
template <bool SAME>
__device__ __forceinline__ void q1_body(const float* __restrict__ I,
                                        int c, int zs, int xy, int oxy) {
    float wl[KW], wq[KW];
#pragma unroll
    for (int t = 0; t < KW; t++) { wl[t] = g_wlif[c][t]; if (!SAME) wq[t] = g_wq[c][t]; }

    const float* uC = g_u + c * VOL;
    float2 rI[KW], rU[KW];
#pragma unroll
    for (int t = 0; t < KW; t++) { rI[t] = make_float2(0.f, 0.f); rU[t] = rI[t]; }

    float* pA = g_pA + (long)c * VOLP * 2;
    float* pQ = g_q + (long)c * VOLP;

#pragma unroll
    for (int k = 0; k < SEG1 + 6; ++k) {
        const int s = zs - 3 + k;
#pragma unroll
        for (int t = 0; t < KW - 1; t++) { rI[t] = rI[t + 1]; rU[t] = rU[t + 1]; }
        float2 uv = make_float2(0.f, 0.f), Iv = uv;
        if (s >= 0 && s < ZD) {
            int gi = s * PL + xy;
            uv = *reinterpret_cast<const float2*>(uC + gi);
            Iv = *reinterpret_cast<const float2*>(I + gi);
        }
        rU[KW - 1] = uv;
        rI[KW - 1] = make_float2(uv.x * Iv.x, uv.y * Iv.y);
        if (k >= 6) {
            int z = s - 3;
            float2 a0 = make_float2(0.f, 0.f), a1 = a0;
#pragma unroll
            for (int t = 0; t < KW; t++) { f2fma(wl[t], rI[t], a0); f2fma(wl[t], rU[t], a1); }
            int oidx = z * PLP + oxy;
            *reinterpret_cast<float4*>(pA + 2 * oidx) = make_float4(a0.x, a1.x, a0.y, a1.y);
            if (!SAME) {
                float2 a2 = make_float2(0.f, 0.f);
#pragma unroll
                for (int t = 0; t < KW; t++) f2fma(wq[t], rU[t], a2);
                *reinterpret_cast<float2*>(pQ + oidx) = a2;
            }
        }
    }
}

__global__ __launch_bounds__(256) void q1(const float* __restrict__ I) {
    const int x2 = blockIdx.x * 32 + threadIdx.x * 2;
    const int y  = blockIdx.y * 16 + threadIdx.y;
    const int bz = blockIdx.z;
    const int c  = bz / NSEG1;
    const int zs = (bz - c * NSEG1) * SEG1;
    const int xy  = y * XD + x2;
    const int oxy = y * XP + x2 + XOFF;
    if (g_same) q1_body<true>(I, c, zs, xy, oxy);
    else        q1_body<false>(I, c, zs, xy, oxy);
}

// dual x-tap: 5 float4 loads from interleaved pair buffer; outputs for both streams
__device__ __forceinline__ void xtap_dual(const float* __restrict__ pb, int e0,
                                          const float* __restrict__ w,
                                          float2& o0, float2& o1) {
    float f0[10], f1[10];
    const float4* p = reinterpret_cast<const float4*>(pb + 2 * (e0 - 4));
#pragma unroll
    for (int j = 0; j < 5; j++) {
        float4 v = p[j];
        f0[2 * j] = v.x; f1[2 * j] = v.y; f0[2 * j + 1] = v.z; f1[2 * j + 1] = v.w;
    }
    o0 = make_float2(0.f, 0.f); o1 = o0;
#pragma unroll
    for (int t = 0; t < KW; t++) {
        o0.x += w[t] * f0[t + 1]; o0.y += w[t] * f0[t + 2];
        o1.x += w[t] * f1[t + 1]; o1.y += w[t] * f1[t + 2];
    }
}

// scalar x-tap pair on non-interleaved buffer (wq stream, !same path)
__device__ __forceinline__ float2 xtap_pair(const float* __restrict__ b, int bidx,
                                            const float* __restrict__ w) {
    float f[10];
    const float2* p = reinterpret_cast<const float2*>(b + bidx - 4);
#pragma unroll
    for (int j = 0; j < 5; j++) { float2 v = p[j]; f[2 * j] = v.x; f[2 * j + 1] = v.y; }
    float2 r = make_float2(0.f, 0.f);
#pragma unroll
    for (int t = 0; t < KW; t++) { r.x += w[t] * f[t + 1]; r.y += w[t] * f[t + 2]; }
    return r;
}

// ============ q2: y-ring + dual x-taps -> (Cn, Cn2) interleaved + C2q ============
template <bool SAME>
__device__ __forceinline__ void q2_body(int c, int ys, int zx) {
    float wl[KW], wq[KW];
#pragma unroll
    for (int t = 0; t < KW; t++) { wl[t] = g_wlif[c][t]; if (!SAME) wq[t] = g_wq[c][t]; }

    const float* pA = g_pA + (long)c * VOLP * 2;
    float* pB = g_pB + (long)c * VOLP * 2;
    float* pQ = g_q + (long)c * VOLP;

    float2 r0[KW], r1[KW], r2[KW];
#pragma unroll
    for (int t = 0; t < KW; t++) {
        r0[t] = make_float2(0.f, 0.f); r1[t] = r0[t];
        if (!SAME) r2[t] = r0[t];
    }

#pragma unroll
    for (int k = 0; k < SEG2 + 6; ++k) {
        const int s = ys - 3 + k;
#pragma unroll
        for (int t = 0; t < KW - 1; t++) {
            r0[t] = r0[t+1]; r1[t] = r1[t+1];
            if (!SAME) r2[t] = r2[t+1];
        }
        float2 v0 = make_float2(0.f, 0.f), v1 = v0, v2 = v0;
        if (s >= 0 && s < YD) {
            int base = zx + s * XP;
            xtap_dual(pA, base, wl, v0, v1);
            if (!SAME) v2 = xtap_pair(pQ, base, wq);
        }
        r0[KW-1] = v0; r1[KW-1] = v1;
        if (!SAME) r2[KW-1] = v2;
        if (k >= 6) {
            int y = s - 3;
            int oidx = zx + y * XP;
            float2 C1 = make_float2(0.f, 0.f), C2 = C1;
#pragma unroll
            for (int t = 0; t < KW; t++) { f2fma(wl[t], r0[t], C1); f2fma(wl[t], r1[t], C2); }
            float2 C2q;
            if (!SAME) {
                C2q = make_float2(0.f, 0.f);
#pragma unroll
                for (int t = 0; t < KW; t++) f2fma(wq[t], r2[t], C2q);
            } else {
                C2q = C2;
            }
            float2 Cn = make_float2((C1.x + 1e-6f) / (C2.x + 1e-6f),
                                    (C1.y + 1e-6f) / (C2.y + 1e-6f));
            *reinterpret_cast<float4*>(pB + 2 * oidx) =
                make_float4(Cn.x, Cn.x * Cn.x, Cn.y, Cn.y * Cn.y);
            *reinterpret_cast<float2*>(pQ + oidx) = C2q;
        }
    }
}

__global__ __launch_bounds__(256) void q2() {
    const int x2 = blockIdx.x * 32 + threadIdx.x * 2;
    const int z  = blockIdx.y * 16 + threadIdx.y;
    const int bz = blockIdx.z;
    const int c  = bz / NSEG2;
    const int ys = (bz - c * NSEG2) * SEG2;
    const int zx = z * PLP + x2 + XOFF;
    if (g_same) q2_body<true>(c, ys, zx);
    else        q2_body<false>(c, ys, zx);
}

// ============ q3: z-ring pointwise conv of interleaved (Cn, Cn2) ============
__global__ __launch_bounds__(256) void q3() {
    const int x2 = blockIdx.x * 32 + threadIdx.x * 2;
    const int y  = blockIdx.y * 16 + threadIdx.y;
    const int bz = blockIdx.z;
    const int c  = bz / NSEG3;
    const int zs = (bz - c * NSEG3) * SEG3;
    const int xy = y * XP + x2 + XOFF;

    float wl[KW];
#pragma unroll
    for (int t = 0; t < KW; t++) wl[t] = g_wlif[c][t];

    const float* pB = g_pB + (long)c * VOLP * 2;
    float* pA = g_pA + (long)c * VOLP * 2;

    float4 r[KW];
#pragma unroll
    for (int t = 0; t < KW; t++) r[t] = make_float4(0.f, 0.f, 0.f, 0.f);

#pragma unroll
    for (int k = 0; k < SEG3 + 6; ++k) {
        const int s = zs - 3 + k;
#pragma unroll
        for (int t = 0; t < KW - 1; t++) r[t] = r[t+1];
        float4 v = make_float4(0.f, 0.f, 0.f, 0.f);
        if (s >= 0 && s < ZD) {
            int gi = s * PLP + xy;
            v = *reinterpret_cast<const float4*>(pB + 2 * gi);
        }
        r[KW-1] = v;
        if (k >= 6) {
            int z = s - 3;
            float4 a = make_float4(0.f, 0.f, 0.f, 0.f);
#pragma unroll
            for (int t = 0; t < KW; t++) f4fma(wl[t], r[t], a);
            int oidx = z * PLP + xy;
            *reinterpret_cast<float4*>(pA + 2 * oidx) = a;
        }
    }
}

// ============ q4: y-ring + x-taps (interleaved E,D), ALL channels, softmax ============
__global__ __launch_bounds__(256) void q4(const float* __restrict__ o,
                                          const float* __restrict__ I,
                                          const float* __restrict__ eta_p,
                                          const float* __restrict__ lam_p,
                                          const float* __restrict__ mu_p,
                                          float* __restrict__ out,
                                          int write_ext) {
    const int x = blockIdx.x * 32 + threadIdx.x;
    const int z = blockIdx.y * 8 + threadIdx.y;
    const int ys = blockIdx.z * SEG4;
    const int zxp = z * PLP + x + XOFF;
    const int zxu = z * PL + x;

    __shared__ float swl[CH][KW];
    {
        int tid = threadIdx.y * 32 + threadIdx.x;
        if (tid < CH * KW) ((float*)swl)[tid] = ((const float*)g_wlif)[tid];
    }
    __syncthreads();

    const float lam = lam_p[0];
    const float mu  = mu_p[0];
    const float inv_eta = 1.f / eta_p[0];

    float slxz[CH], sqxz[CH];
#pragma unroll
    for (int c = 0; c < CH; c++) {
        slxz[c] = g_slif[c][x] * g_slif[c][z];
        sqxz[c] = g_sq[c][x] * g_sq[c][z];
    }

    float2 rP[CH][KW];   // (E,D) rings
#pragma unroll
    for (int c = 0; c < CH; c++)
#pragma unroll
        for (int t = 0; t < KW; t++) rP[c][t] = make_float2(0.f, 0.f);

    float* dst = write_ext ? out : g_u;

#pragma unroll
    for (int k = 0; k < SEG4 + 6; ++k) {
        const int s = ys - 3 + k;
#pragma unroll
        for (int c = 0; c < CH; c++)
#pragma unroll
            for (int t = 0; t < KW - 1; t++) rP[c][t] = rP[c][t+1];

        if (s >= 0 && s < YD) {
            int base = zxp + s * XP;
#pragma unroll
            for (int c = 0; c < CH; c++) {
                const float2* bP = reinterpret_cast<const float2*>(g_pA) + (long)c * VOLP;
                float2 acc = make_float2(0.f, 0.f);
#pragma unroll
                for (int t = 0; t < KW; t++) {
                    float2 v = bP[base + t - 3];
                    acc.x += swl[c][t] * v.x;
                    acc.y += swl[c][t] * v.y;
                }
                rP[c][KW-1] = acc;
            }
        } else {
#pragma unroll
            for (int c = 0; c < CH; c++) rP[c][KW-1] = make_float2(0.f, 0.f);
        }

        if (k >= 6) {
            int y = s - 3;
            int iu = zxu + y * XD;
            int ip = zxp + y * XP;
            float Iv = I[iu];
            float a[CH];
#pragma unroll
            for (int c = 0; c < CH; c++) {
                float E = 0.f, D = 0.f;
#pragma unroll
                for (int t = 0; t < KW; t++) {
                    E += swl[c][t] * rP[c][t].x;
                    D += swl[c][t] * rP[c][t].y;
                }
                float cones = slxz[c] * g_slif[c][y];
                float Lif = D - 2.f * Iv * E + Iv * Iv * cones;
                float q = sqxz[c] * g_sq[c][y] - 2.f * g_q[(long)c * VOLP + ip];
                a[c] = (o[c * VOL + iu] - mu * Lif - lam * q) * inv_eta;
            }
            float m = fmaxf(fmaxf(a[0], a[1]), fmaxf(a[2], a[3]));
            float e0 = expf(a[0] - m), e1 = expf(a[1] - m);
            float e2 = expf(a[2] - m), e3 = expf(a[3] - m);
            float inv = 1.f / (e0 + e1 + e2 + e3);
            dst[iu] = e0 * inv;
            dst[VOL + iu] = e1 * inv;
            dst[2 * VOL + iu] = e2 * inv;
            dst[3 * VOL + iu] = e3 * inv;
        }
    }
}

// ---------------- launch ----------------
extern "C" void kernel_launch(void* const* d_in, const int* in_sizes, int n_in,
                              void* d_out, int out_size) {
    const float* o      = (const float*)d_in[0];
    const float* I      = (const float*)d_in[1];
    const float* sigma2 = (const float*)d_in[2];
    const float* sigma3 = (const float*)d_in[3];
    const float* eta    = (const float*)d_in[4];
    const float* lam    = (const float*)d_in[5];
    const float* mu     = (const float*)d_in[6];
    float* out = (float*)d_out;

    const int Tpt = 256;
    const int Bpt = (VOL + Tpt - 1) / Tpt;

    k_setup<<<1, 32>>>(sigma2, sigma3);
    k_init<<<Bpt, Tpt>>>(o, eta);
    {
        long padtotal = (long)CH * ZD * YD * 8;
        int zb = (int)((padtotal + 255) / 256);
        k_zeropad<<<zb, 256>>>();
    }

    dim3 blkV(16, 16);
    dim3 blkS(32, 8);
    dim3 grid1(3, 6, NSEG1 * CH);   // 1152
    dim3 grid2(3, 6, NSEG2 * CH);   // 864
    dim3 grid3(3, 6, NSEG3 * CH);   // 1152
    dim3 grid4(3, 12, NSEG4);       // 576

    const int NB_ITERS = 10;
    for (int it = 0; it < NB_ITERS; ++it) {
        q1<<<grid1, blkV>>>(I);
        q2<<<grid2, blkV>>>();
        q3<<<grid3, blkV>>>();
        q4<<<grid4, blkS>>>(o, I, eta, lam, mu, out, (it == NB_ITERS - 1) ? 1 : 0);
    }
}

// round 10
// speedup vs baseline: 1.0178x; 1.0178x over previous
#include <cuda_runtime.h>

// Problem dims
#define ZD 96
#define YD 96
#define XD 96
#define PL 9216
#define VOL 884736
#define CH 4
#define KW 7

// Padded x-layout for intermediates
#define XP 104
#define XOFF 4
#define PLP (YD * XP)
#define VOLP (ZD * PLP)

// Segment configs
#define SEG1 8
#define NSEG1 12
#define SEG2 8
#define NSEG2 12
#define SEG3 8
#define NSEG3 12
#define SEG4 8
#define NSEG4 12

// ---------------- persistent device scratch ----------------
__device__ float g_wlif[CH][KW];
__device__ float g_wq[CH][KW];
__device__ float g_slif[CH][ZD];
__device__ float g_sq[CH][ZD];
__device__ int   g_same;
__device__ float g_u[CH * VOL];
__device__ float g_bufA[3 * CH * VOLP];
__device__ float g_bufB[3 * CH * VOLP];

// ---------------- zero the x-pad halos ----------------
__global__ void k_zeropad() {
    long nrows = (long)3 * CH * ZD * YD;
    long idx = (long)blockIdx.x * blockDim.x + threadIdx.x;
    long total = nrows * 8;
    if (idx >= total) return;
    long row = idx >> 3;
    int p = (int)(idx & 7);
    int xo = (p < 4) ? p : (XOFF + XD + p - 4);
    g_bufA[row * XP + xo] = 0.f;
    g_bufB[row * XP + xo] = 0.f;
}

// ---------------- setup ----------------
__global__ void k_setup(const float* __restrict__ sigma2,
                        const float* __restrict__ sigma3) {
    int c = threadIdx.x;
    if (c == 0) {
        int s = 1;
        for (int k = 0; k < CH; k++) s &= (sigma2[k] == sigma3[k]);
        g_same = s;
    }
    if (c < CH) {
        float s2 = sigma2[c], s3 = sigma3[c];
        float w2[KW], w3[KW];
        float sum2 = 0.f, sum3 = 0.f;
        for (int t = 0; t < KW; t++) {
            float d = (float)(t - 3);
            w2[t] = expf(-d * d / (2.f * s2 * s2)); sum2 += w2[t];
            w3[t] = expf(-d * d / (2.f * s3 * s3)); sum3 += w3[t];
        }
        for (int t = 0; t < KW; t++) {
            g_wq[c][t]   = w2[t] / sum2;
            g_wlif[c][t] = w3[t] / sum3;
        }
        for (int p = 0; p < ZD; p++) {
            float sl = 0.f, sq = 0.f;
            for (int t = 0; t < KW; t++) {
                int q = p + t - 3;
                if (q >= 0 && q < ZD) { sl += g_wlif[c][t]; sq += g_wq[c][t]; }
            }
            g_slif[c][p] = sl;
            g_sq[c][p]   = sq;
        }
    }
}

// ---------------- u0 = softmax(o / eta) ----------------
__global__ void k_init(const float* __restrict__ o,
                       const float* __restrict__ eta_p) {
    int i = blockIdx.x * blockDim.x + threadIdx.x;
    if (i >= VOL) return;
    float inv_eta = 1.f / eta_p[0];
    float a0 = o[i] * inv_eta;
    float a1 = o[VOL + i] * inv_eta;
    float a2 = o[2 * VOL + i] * inv_eta;
    float a3 = o[3 * VOL + i] * inv_eta;
    float m = fmaxf(fmaxf(a0, a1), fmaxf(a2, a3));
    float e0 = expf(a0 - m), e1 = expf(a1 - m), e2 = expf(a2 - m), e3 = expf(a3 - m);
    float inv = 1.f / (e0 + e1 + e2 + e3);
    g_u[i] = e0 * inv;
    g_u[VOL + i] = e1 * inv;
    g_u[2 * VOL + i] = e2 * inv;
    g_u[3 * VOL + i] = e3 * inv;
}

__device__ __forceinline__ void f2fma(float w, float2 v, float2& acc) {
    acc.x += w * v.x; acc.y += w * v.y;
}

// ============ q1: z-ring conv of {u*I, u} — float2, templated on SAME ============
template <bool SAME>
__device__ __forceinline__ void q1_body(const float* __restrict__ I,
                                        int c, int zs, int xy, int oxy) {
    float wl[KW], wq[KW];
#pragma unroll
    for (int t = 0; t < KW; t++) { wl[t] = g_wlif[c][t]; if (!SAME) wq[t] = g_wq[c][t]; }

    const float* uC = g_u + c * VOL;
    float2 rI[KW], rU[KW];
#pragma unroll
    for (int t = 0; t < KW; t++) { rI[t] = make_float2(0.f, 0.f); rU[t] = rI[t]; }

#pragma unroll
    for (int k = 0; k < SEG1 + 6; ++k) {
        const int s = zs - 3 + k;
#pragma unroll
        for (int t = 0; t < KW - 1; t++) { rI[t] = rI[t + 1]; rU[t] = rU[t + 1]; }
        float2 uv = make_float2(0.f, 0.f), Iv = uv;
        if (s >= 0 && s < ZD) {
            int gi = s * PL + xy;
            uv = *reinterpret_cast<const float2*>(uC + gi);
            Iv = *reinterpret_cast<const float2*>(I + gi);
        }
        rU[KW - 1] = uv;
        rI[KW - 1] = make_float2(uv.x * Iv.x, uv.y * Iv.y);
        if (k >= 6) {
            int z = s - 3;
            float2 a0 = make_float2(0.f, 0.f), a1 = a0;
#pragma unroll
            for (int t = 0; t < KW; t++) { f2fma(wl[t], rI[t], a0); f2fma(wl[t], rU[t], a1); }
            int oidx = z * PLP + oxy;
            *reinterpret_cast<float2*>(g_bufA + (0 * CH + c) * VOLP + oidx) = a0;
            *reinterpret_cast<float2*>(g_bufA + (1 * CH + c) * VOLP + oidx) = a1;
            if (!SAME) {
                float2 a2 = make_float2(0.f, 0.f);
#pragma unroll
                for (int t = 0; t < KW; t++) f2fma(wq[t], rU[t], a2);
                *reinterpret_cast<float2*>(g_bufA + (2 * CH + c) * VOLP + oidx) = a2;
            }
        }
    }
}

__global__ __launch_bounds__(256, 5) void q1(const float* __restrict__ I) {
    const int x2 = blockIdx.x * 32 + threadIdx.x * 2;
    const int y  = blockIdx.y * 16 + threadIdx.y;
    const int bz = blockIdx.z;
    const int c  = bz / NSEG1;
    const int zs = (bz - c * NSEG1) * SEG1;
    const int xy  = y * XD + x2;
    const int oxy = y * XP + x2 + XOFF;
    if (g_same) q1_body<true>(I, c, zs, xy, oxy);
    else        q1_body<false>(I, c, zs, xy, oxy);
}

// x-tap pair: 5 aligned float2 loads
__device__ __forceinline__ float2 xtap_pair(const float* __restrict__ b, int bidx,
                                            const float* __restrict__ w) {
    float f[10];
    const float2* p = reinterpret_cast<const float2*>(b + bidx - 4);
#pragma unroll
    for (int j = 0; j < 5; j++) { float2 v = p[j]; f[2 * j] = v.x; f[2 * j + 1] = v.y; }
    float2 r = make_float2(0.f, 0.f);
#pragma unroll
    for (int t = 0; t < KW; t++) { r.x += w[t] * f[t + 1]; r.y += w[t] * f[t + 2]; }
    return r;
}

// ============ q2: y-ring + x-tap pairs -> Cn, Cn^2, C2q — templated ============
template <bool SAME>
__device__ __forceinline__ void q2_body(int c, int ys, int zx) {
    float wl[KW], wq[KW];
#pragma unroll
    for (int t = 0; t < KW; t++) { wl[t] = g_wlif[c][t]; if (!SAME) wq[t] = g_wq[c][t]; }

    const float* b0 = g_bufA + (0 * CH + c) * VOLP;
    const float* b1 = g_bufA + (1 * CH + c) * VOLP;
    const float* b2 = g_bufA + (2 * CH + c) * VOLP;

    float2 r0[KW], r1[KW], r2[KW];
#pragma unroll
    for (int t = 0; t < KW; t++) {
        r0[t] = make_float2(0.f, 0.f); r1[t] = r0[t];
        if (!SAME) r2[t] = r0[t];
    }

#pragma unroll
    for (int k = 0; k < SEG2 + 6; ++k) {
        const int s = ys - 3 + k;
#pragma unroll
        for (int t = 0; t < KW - 1; t++) {
            r0[t] = r0[t+1]; r1[t] = r1[t+1];
            if (!SAME) r2[t] = r2[t+1];
        }
        float2 v0 = make_float2(0.f, 0.f), v1 = v0, v2 = v0;
        if (s >= 0 && s < YD) {
            int base = zx + s * XP;
            v0 = xtap_pair(b0, base, wl);
            v1 = xtap_pair(b1, base, wl);
            if (!SAME) v2 = xtap_pair(b2, base, wq);
        }
        r0[KW-1] = v0; r1[KW-1] = v1;
        if (!SAME) r2[KW-1] = v2;
        if (k >= 6) {
            int y = s - 3;
            int oidx = zx + y * XP;
            float2 C1 = make_float2(0.f, 0.f), C2 = C1;
#pragma unroll
            for (int t = 0; t < KW; t++) { f2fma(wl[t], r0[t], C1); f2fma(wl[t], r1[t], C2); }
            float2 C2q;
            if (!SAME) {
                C2q = make_float2(0.f, 0.f);
#pragma unroll
                for (int t = 0; t < KW; t++) f2fma(wq[t], r2[t], C2q);
            } else {
                C2q = C2;
            }
            float2 Cn = make_float2((C1.x + 1e-6f) / (C2.x + 1e-6f),
                                    (C1.y + 1e-6f) / (C2.y + 1e-6f));
            *reinterpret_cast<float2*>(g_bufB + (0 * CH + c) * VOLP + oidx) = Cn;
            *reinterpret_cast<float2*>(g_bufB + (1 * CH + c) * VOLP + oidx) =
                make_float2(Cn.x * Cn.x, Cn.y * Cn.y);
            *reinterpret_cast<float2*>(g_bufB + (2 * CH + c) * VOLP + oidx) = C2q;
        }
    }
}

__global__ __launch_bounds__(256, 4) void q2() {
    const int x2 = blockIdx.x * 32 + threadIdx.x * 2;
    const int z  = blockIdx.y * 16 + threadIdx.y;
    const int bz = blockIdx.z;
    const int c  = bz / NSEG2;
    const int ys = (bz - c * NSEG2) * SEG2;
    const int zx = z * PLP + x2 + XOFF;
    if (g_same) q2_body<true>(c, ys, zx);
    else        q2_body<false>(c, ys, zx);
}

// ============ q3: z-ring pointwise conv of {Cn, Cn^2} — float2 ============
__global__ __launch_bounds__(256, 5) void q3() {
    const int x2 = blockIdx.x * 32 + threadIdx.x * 2;
    const int y  = blockIdx.y * 16 + threadIdx.y;
    const int bz = blockIdx.z;
    const int c  = bz / NSEG3;
    const int zs = (bz - c * NSEG3) * SEG3;
    const int xy = y * XP + x2 + XOFF;

    float wl[KW];
#pragma unroll
    for (int t = 0; t < KW; t++) wl[t] = g_wlif[c][t];

    const float* b0 = g_bufB + (0 * CH + c) * VOLP;
    const float* b1 = g_bufB + (1 * CH + c) * VOLP;

    float2 r0[KW], r1[KW];
#pragma unroll
    for (int t = 0; t < KW; t++) { r0[t] = make_float2(0.f, 0.f); r1[t] = r0[t]; }

#pragma unroll
    for (int k = 0; k < SEG3 + 6; ++k) {
        const int s = zs - 3 + k;
#pragma unroll
        for (int t = 0; t < KW - 1; t++) { r0[t] = r0[t+1]; r1[t] = r1[t+1]; }
        float2 v0 = make_float2(0.f, 0.f), v1 = v0;
        if (s >= 0 && s < ZD) {
            int gi = s * PLP + xy;
            v0 = *reinterpret_cast<const float2*>(b0 + gi);
            v1 = *reinterpret_cast<const float2*>(b1 + gi);
        }
        r0[KW-1] = v0; r1[KW-1] = v1;
        if (k >= 6) {
            int z = s - 3;
            float2 a0 = make_float2(0.f, 0.f), a1 = a0;
#pragma unroll
            for (int t = 0; t < KW; t++) { f2fma(wl[t], r0[t], a0); f2fma(wl[t], r1[t], a1); }
            int oidx = z * PLP + xy;
            *reinterpret_cast<float2*>(g_bufA + (0 * CH + c) * VOLP + oidx) = a0;
            *reinterpret_cast<float2*>(g_bufA + (1 * CH + c) * VOLP + oidx) = a1;
        }
    }
}

// ============ q4: y-ring + x-taps, ALL channels, Lif + q + softmax ============
__global__ __launch_bounds__(256) void q4(const float* __restrict__ o,
                                          const float* __restrict__ I,
                                          const float* __restrict__ eta_p,
                                          const float* __restrict__ lam_p,
                                          const float* __restrict__ mu_p,
                                          float* __restrict__ out,
                                          int write_ext) {
    const int x = blockIdx.x * 32 + threadIdx.x;
    const int z = blockIdx.y * 8 + threadIdx.y;
    const int ys = blockIdx.z * SEG4;
    const int zxp = z * PLP + x + XOFF;
    const int zxu = z * PL + x;

    __shared__ float swl[CH][KW];
    {
        int tid = threadIdx.y * 32 + threadIdx.x;
        if (tid < CH * KW) ((float*)swl)[tid] = ((const float*)g_wlif)[tid];
    }
    __syncthreads();

    const float lam = lam_p[0];
    const float mu  = mu_p[0];
    const float inv_eta = 1.f / eta_p[0];

    float slxz[CH], sqxz[CH];
#pragma unroll
    for (int c = 0; c < CH; c++) {
        slxz[c] = g_slif[c][x] * g_slif[c][z];
        sqxz[c] = g_sq[c][x] * g_sq[c][z];
    }

    float rE[CH][KW], rD[CH][KW];
#pragma unroll
    for (int c = 0; c < CH; c++)
#pragma unroll
        for (int t = 0; t < KW; t++) { rE[c][t] = 0.f; rD[c][t] = 0.f; }

    float* dst = write_ext ? out : g_u;

#pragma unroll
    for (int k = 0; k < SEG4 + 6; ++k) {
        const int s = ys - 3 + k;
#pragma unroll
        for (int c = 0; c < CH; c++)
#pragma unroll
            for (int t = 0; t < KW - 1; t++) { rE[c][t] = rE[c][t+1]; rD[c][t] = rD[c][t+1]; }

        if (s >= 0 && s < YD) {
            int base = zxp + s * XP;
#pragma unroll
            for (int c = 0; c < CH; c++) {
                const float* bE = g_bufA + (0 * CH + c) * VOLP;
                const float* bD = g_bufA + (1 * CH + c) * VOLP;
                float vE = 0.f, vD = 0.f;
#pragma unroll
                for (int t = 0; t < KW; t++) {
                    float w = swl[c][t];
                    vE += w * bE[base + t - 3];
                    vD += w * bD[base + t - 3];
                }
                rE[c][KW-1] = vE; rD[c][KW-1] = vD;
            }
        } else {
#pragma unroll
            for (int c = 0; c < CH; c++) { rE[c][KW-1] = 0.f; rD[c][KW-1] = 0.f; }
        }

        if (k >= 6) {
            int y = s - 3;
            int iu = zxu + y * XD;
            int ip = zxp + y * XP;
            float Iv = I[iu];
            float a[CH];
#pragma unroll
            for (int c = 0; c < CH; c++) {
                float E = 0.f, D = 0.f;
#pragma unroll
                for (int t = 0; t < KW; t++) {
                    float w = swl[c][t];
                    E += w * rE[c][t]; D += w * rD[c][t];
                }
                float cones = slxz[c] * g_slif[c][y];
                float Lif = D - 2.f * Iv * E + Iv * Iv * cones;
                float q = sqxz[c] * g_sq[c][y] - 2.f * g_bufB[(2 * CH + c) * VOLP + ip];
                a[c] = (o[c * VOL + iu] - mu * Lif - lam * q) * inv_eta;
            }
            float m = fmaxf(fmaxf(a[0], a[1]), fmaxf(a[2], a[3]));
            float e0 = expf(a[0] - m), e1 = expf(a[1] - m);
            float e2 = expf(a[2] - m), e3 = expf(a[3] - m);
            float inv = 1.f / (e0 + e1 + e2 + e3);
            dst[iu] = e0 * inv;
            dst[VOL + iu] = e1 * inv;
            dst[2 * VOL + iu] = e2 * inv;
            dst[3 * VOL + iu] = e3 * inv;
        }
    }
}

// ---------------- launch ----------------
extern "C" void kernel_launch(void* const* d_in, const int* in_sizes, int n_in,
                              void* d_out, int out_size) {
    const float* o      = (const float*)d_in[0];
    const float* I      = (const float*)d_in[1];
    const float* sigma2 = (const float*)d_in[2];
    const float* sigma3 = (const float*)d_in[3];
    const float* eta    = (const float*)d_in[4];
    const float* lam    = (const float*)d_in[5];
    const float* mu     = (const float*)d_in[6];
    float* out = (float*)d_out;

    const int Tpt = 256;
    const int Bpt = (VOL + Tpt - 1) / Tpt;

    k_setup<<<1, 32>>>(sigma2, sigma3);
    k_init<<<Bpt, Tpt>>>(o, eta);
    {
        long padtotal = (long)3 * CH * ZD * YD * 8;
        int zb = (int)((padtotal + 255) / 256);
        k_zeropad<<<zb, 256>>>();
    }

    dim3 blkV(16, 16);
    dim3 blkS(32, 8);
    dim3 grid1(3, 6, NSEG1 * CH);   // 864
    dim3 grid2(3, 6, NSEG2 * CH);   // 864
    dim3 grid3(3, 6, NSEG3 * CH);   // 864
    dim3 grid4(3, 12, NSEG4);       // 432

    const int NB_ITERS = 10;
    for (int it = 0; it < NB_ITERS; ++it) {
        q1<<<grid1, blkV>>>(I);
        q2<<<grid2, blkV>>>();
        q3<<<grid3, blkV>>>();
        q4<<<grid4, blkS>>>(o, I, eta, lam, mu, out, (it == NB_ITERS - 1) ? 1 : 0);
    }
}

// round 11
// speedup vs baseline: 1.1015x; 1.0822x over previous
#include <cuda_runtime.h>

// Problem dims
#define ZD 96
#define YD 96
#define XD 96
#define PL 9216
#define VOL 884736
#define CH 4
#define KW 7

// Padded x-layout for intermediates
#define XP 104
#define XOFF 4
#define PLP (YD * XP)
#define VOLP (ZD * PLP)

// Segment configs (wave-aware: grid ≈ k * 148 * blocks_per_SM)
#define SEG1 6
#define NSEG1 16
#define SEG2 8
#define NSEG2 12
#define SEG3 6
#define NSEG3 16
#define SEG4 8
#define NSEG4 12

// ---------------- persistent device scratch ----------------
__device__ float g_wlif[CH][KW];
__device__ float g_wq[CH][KW];
__device__ float g_slif[CH][ZD];
__device__ float g_sq[CH][ZD];
__device__ int   g_same;
__device__ float g_u[CH * VOL];
__device__ float g_bufA[3 * CH * VOLP];
__device__ float g_bufB[3 * CH * VOLP];

// ---------------- zero the x-pad halos ----------------
__global__ void k_zeropad() {
    long nrows = (long)3 * CH * ZD * YD;
    long idx = (long)blockIdx.x * blockDim.x + threadIdx.x;
    long total = nrows * 8;
    if (idx >= total) return;
    long row = idx >> 3;
    int p = (int)(idx & 7);
    int xo = (p < 4) ? p : (XOFF + XD + p - 4);
    g_bufA[row * XP + xo] = 0.f;
    g_bufB[row * XP + xo] = 0.f;
}

// ---------------- setup ----------------
__global__ void k_setup(const float* __restrict__ sigma2,
                        const float* __restrict__ sigma3) {
    int c = threadIdx.x;
    if (c == 0) {
        int s = 1;
        for (int k = 0; k < CH; k++) s &= (sigma2[k] == sigma3[k]);
        g_same = s;
    }
    if (c < CH) {
        float s2 = sigma2[c], s3 = sigma3[c];
        float w2[KW], w3[KW];
        float sum2 = 0.f, sum3 = 0.f;
        for (int t = 0; t < KW; t++) {
            float d = (float)(t - 3);
            w2[t] = expf(-d * d / (2.f * s2 * s2)); sum2 += w2[t];
            w3[t] = expf(-d * d / (2.f * s3 * s3)); sum3 += w3[t];
        }
        for (int t = 0; t < KW; t++) {
            g_wq[c][t]   = w2[t] / sum2;
            g_wlif[c][t] = w3[t] / sum3;
        }
        for (int p = 0; p < ZD; p++) {
            float sl = 0.f, sq = 0.f;
            for (int t = 0; t < KW; t++) {
                int q = p + t - 3;
                if (q >= 0 && q < ZD) { sl += g_wlif[c][t]; sq += g_wq[c][t]; }
            }
            g_slif[c][p] = sl;
            g_sq[c][p]   = sq;
        }
    }
}

// ---------------- u0 = softmax(o / eta) ----------------
__global__ void k_init(const float* __restrict__ o,
                       const float* __restrict__ eta_p) {
    int i = blockIdx.x * blockDim.x + threadIdx.x;
    if (i >= VOL) return;
    float inv_eta = 1.f / eta_p[0];
    float a0 = o[i] * inv_eta;
    float a1 = o[VOL + i] * inv_eta;
    float a2 = o[2 * VOL + i] * inv_eta;
    float a3 = o[3 * VOL + i] * inv_eta;
    float m = fmaxf(fmaxf(a0, a1), fmaxf(a2, a3));
    float e0 = expf(a0 - m), e1 = expf(a1 - m), e2 = expf(a2 - m), e3 = expf(a3 - m);
    float inv = 1.f / (e0 + e1 + e2 + e3);
    g_u[i] = e0 * inv;
    g_u[VOL + i] = e1 * inv;
    g_u[2 * VOL + i] = e2 * inv;
    g_u[3 * VOL + i] = e3 * inv;
}

__device__ __forceinline__ void f2fma(float w, float2 v, float2& acc) {
    acc.x += w * v.x; acc.y += w * v.y;
}

// ============ q1: z-ring conv of {u*I, u} — float2 (R8 config) ============
template <bool SAME>
__device__ __forceinline__ void q1_body(const float* __restrict__ I,
                                        int c, int zs, int xy, int oxy) {
    float wl[KW], wq[KW];
#pragma unroll
    for (int t = 0; t < KW; t++) { wl[t] = g_wlif[c][t]; if (!SAME) wq[t] = g_wq[c][t]; }

    const float* uC = g_u + c * VOL;
    float2 rI[KW], rU[KW];
#pragma unroll
    for (int t = 0; t < KW; t++) { rI[t] = make_float2(0.f, 0.f); rU[t] = rI[t]; }

#pragma unroll
    for (int k = 0; k < SEG1 + 6; ++k) {
        const int s = zs - 3 + k;
#pragma unroll
        for (int t = 0; t < KW - 1; t++) { rI[t] = rI[t + 1]; rU[t] = rU[t + 1]; }
        float2 uv = make_float2(0.f, 0.f), Iv = uv;
        if (s >= 0 && s < ZD) {
            int gi = s * PL + xy;
            uv = *reinterpret_cast<const float2*>(uC + gi);
            Iv = *reinterpret_cast<const float2*>(I + gi);
        }
        rU[KW - 1] = uv;
        rI[KW - 1] = make_float2(uv.x * Iv.x, uv.y * Iv.y);
        if (k >= 6) {
            int z = s - 3;
            float2 a0 = make_float2(0.f, 0.f), a1 = a0;
#pragma unroll
            for (int t = 0; t < KW; t++) { f2fma(wl[t], rI[t], a0); f2fma(wl[t], rU[t], a1); }
            int oidx = z * PLP + oxy;
            *reinterpret_cast<float2*>(g_bufA + (0 * CH + c) * VOLP + oidx) = a0;
            *reinterpret_cast<float2*>(g_bufA + (1 * CH + c) * VOLP + oidx) = a1;
            if (!SAME) {
                float2 a2 = make_float2(0.f, 0.f);
#pragma unroll
                for (int t = 0; t < KW; t++) f2fma(wq[t], rU[t], a2);
                *reinterpret_cast<float2*>(g_bufA + (2 * CH + c) * VOLP + oidx) = a2;
            }
        }
    }
}

__global__ __launch_bounds__(256) void q1(const float* __restrict__ I) {
    const int x2 = blockIdx.x * 32 + threadIdx.x * 2;
    const int y  = blockIdx.y * 16 + threadIdx.y;
    const int bz = blockIdx.z;
    const int c  = bz / NSEG1;
    const int zs = (bz - c * NSEG1) * SEG1;
    const int xy  = y * XD + x2;
    const int oxy = y * XP + x2 + XOFF;
    if (g_same) q1_body<true>(I, c, zs, xy, oxy);
    else        q1_body<false>(I, c, zs, xy, oxy);
}

// x-tap pair: 5 aligned float2 loads
__device__ __forceinline__ float2 xtap_pair(const float* __restrict__ b, int bidx,
                                            const float* __restrict__ w) {
    float f[10];
    const float2* p = reinterpret_cast<const float2*>(b + bidx - 4);
#pragma unroll
    for (int j = 0; j < 5; j++) { float2 v = p[j]; f[2 * j] = v.x; f[2 * j + 1] = v.y; }
    float2 r = make_float2(0.f, 0.f);
#pragma unroll
    for (int t = 0; t < KW; t++) { r.x += w[t] * f[t + 1]; r.y += w[t] * f[t + 2]; }
    return r;
}

// ============ q2: y-ring + x-tap pairs -> Cn, Cn^2, C2q (R8 config) ============
template <bool SAME>
__device__ __forceinline__ void q2_body(int c, int ys, int zx) {
    float wl[KW], wq[KW];
#pragma unroll
    for (int t = 0; t < KW; t++) { wl[t] = g_wlif[c][t]; if (!SAME) wq[t] = g_wq[c][t]; }

    const float* b0 = g_bufA + (0 * CH + c) * VOLP;
    const float* b1 = g_bufA + (1 * CH + c) * VOLP;
    const float* b2 = g_bufA + (2 * CH + c) * VOLP;

    float2 r0[KW], r1[KW], r2[KW];
#pragma unroll
    for (int t = 0; t < KW; t++) {
        r0[t] = make_float2(0.f, 0.f); r1[t] = r0[t];
        if (!SAME) r2[t] = r0[t];
    }

#pragma unroll
    for (int k = 0; k < SEG2 + 6; ++k) {
        const int s = ys - 3 + k;
#pragma unroll
        for (int t = 0; t < KW - 1; t++) {
            r0[t] = r0[t+1]; r1[t] = r1[t+1];
            if (!SAME) r2[t] = r2[t+1];
        }
        float2 v0 = make_float2(0.f, 0.f), v1 = v0, v2 = v0;
        if (s >= 0 && s < YD) {
            int base = zx + s * XP;
            v0 = xtap_pair(b0, base, wl);
            v1 = xtap_pair(b1, base, wl);
            if (!SAME) v2 = xtap_pair(b2, base, wq);
        }
        r0[KW-1] = v0; r1[KW-1] = v1;
        if (!SAME) r2[KW-1] = v2;
        if (k >= 6) {
            int y = s - 3;
            int oidx = zx + y * XP;
            float2 C1 = make_float2(0.f, 0.f), C2 = C1;
#pragma unroll
            for (int t = 0; t < KW; t++) { f2fma(wl[t], r0[t], C1); f2fma(wl[t], r1[t], C2); }
            float2 C2q;
            if (!SAME) {
                C2q = make_float2(0.f, 0.f);
#pragma unroll
                for (int t = 0; t < KW; t++) f2fma(wq[t], r2[t], C2q);
            } else {
                C2q = C2;
            }
            float2 Cn = make_float2((C1.x + 1e-6f) / (C2.x + 1e-6f),
                                    (C1.y + 1e-6f) / (C2.y + 1e-6f));
            *reinterpret_cast<float2*>(g_bufB + (0 * CH + c) * VOLP + oidx) = Cn;
            *reinterpret_cast<float2*>(g_bufB + (1 * CH + c) * VOLP + oidx) =
                make_float2(Cn.x * Cn.x, Cn.y * Cn.y);
            *reinterpret_cast<float2*>(g_bufB + (2 * CH + c) * VOLP + oidx) = C2q;
        }
    }
}

__global__ __launch_bounds__(256) void q2() {
    const int x2 = blockIdx.x * 32 + threadIdx.x * 2;
    const int z  = blockIdx.y * 16 + threadIdx.y;
    const int bz = blockIdx.z;
    const int c  = bz / NSEG2;
    const int ys = (bz - c * NSEG2) * SEG2;
    const int zx = z * PLP + x2 + XOFF;
    if (g_same) q2_body<true>(c, ys, zx);
    else        q2_body<false>(c, ys, zx);
}

// ============ q3: z-ring + x-taps of {Cn, Cn^2} -> xz-conv'd ============
__global__ __launch_bounds__(256, 4) void q3() {
    const int x2 = blockIdx.x * 32 + threadIdx.x * 2;
    const int y  = blockIdx.y * 16 + threadIdx.y;
    const int bz = blockIdx.z;
    const int c  = bz / NSEG3;
    const int zs = (bz - c * NSEG3) * SEG3;
    const int xy = y * XP + x2 + XOFF;

    float wl[KW];
#pragma unroll
    for (int t = 0; t < KW; t++) wl[t] = g_wlif[c][t];

    const float* b0 = g_bufB + (0 * CH + c) * VOLP;
    const float* b1 = g_bufB + (1 * CH + c) * VOLP;

    float2 r0[KW], r1[KW];
#pragma unroll
    for (int t = 0; t < KW; t++) { r0[t] = make_float2(0.f, 0.f); r1[t] = r0[t]; }

#pragma unroll
    for (int k = 0; k < SEG3 + 6; ++k) {
        const int s = zs - 3 + k;
#pragma unroll
        for (int t = 0; t < KW - 1; t++) { r0[t] = r0[t+1]; r1[t] = r1[t+1]; }
        float2 v0 = make_float2(0.f, 0.f), v1 = v0;
        if (s >= 0 && s < ZD) {
            int gi = s * PLP + xy;
            v0 = xtap_pair(b0, gi, wl);   // x-conv folded into z-walk load
            v1 = xtap_pair(b1, gi, wl);
        }
        r0[KW-1] = v0; r1[KW-1] = v1;
        if (k >= 6) {
            int z = s - 3;
            float2 a0 = make_float2(0.f, 0.f), a1 = a0;
#pragma unroll
            for (int t = 0; t < KW; t++) { f2fma(wl[t], r0[t], a0); f2fma(wl[t], r1[t], a1); }
            int oidx = z * PLP + xy;
            *reinterpret_cast<float2*>(g_bufA + (0 * CH + c) * VOLP + oidx) = a0;   // wx∘wz∘Cn
            *reinterpret_cast<float2*>(g_bufA + (1 * CH + c) * VOLP + oidx) = a1;   // wx∘wz∘Cn²
        }
    }
}

// ============ q4: y-ring (plain loads), ALL channels, Lif + q + softmax ============
__global__ __launch_bounds__(256, 3) void q4(const float* __restrict__ o,
                                             const float* __restrict__ I,
                                             const float* __restrict__ eta_p,
                                             const float* __restrict__ lam_p,
                                             const float* __restrict__ mu_p,
                                             float* __restrict__ out,
                                             int write_ext) {
    const int x = blockIdx.x * 32 + threadIdx.x;
    const int z = blockIdx.y * 8 + threadIdx.y;
    const int ys = blockIdx.z * SEG4;
    const int zxp = z * PLP + x + XOFF;
    const int zxu = z * PL + x;

    __shared__ float swl[CH][KW];
    {
        int tid = threadIdx.y * 32 + threadIdx.x;
        if (tid < CH * KW) ((float*)swl)[tid] = ((const float*)g_wlif)[tid];
    }
    __syncthreads();

    const float lam = lam_p[0];
    const float mu  = mu_p[0];
    const float inv_eta = 1.f / eta_p[0];

    float slxz[CH], sqxz[CH];
#pragma unroll
    for (int c = 0; c < CH; c++) {
        slxz[c] = g_slif[c][x] * g_slif[c][z];
        sqxz[c] = g_sq[c][x] * g_sq[c][z];
    }

    float rE[CH][KW], rD[CH][KW];
#pragma unroll
    for (int c = 0; c < CH; c++)
#pragma unroll
        for (int t = 0; t < KW; t++) { rE[c][t] = 0.f; rD[c][t] = 0.f; }

    float* dst = write_ext ? out : g_u;

#pragma unroll
    for (int k = 0; k < SEG4 + 6; ++k) {
        const int s = ys - 3 + k;
#pragma unroll
        for (int c = 0; c < CH; c++)
#pragma unroll
            for (int t = 0; t < KW - 1; t++) { rE[c][t] = rE[c][t+1]; rD[c][t] = rD[c][t+1]; }

        if (s >= 0 && s < YD) {
            int base = zxp + s * XP;
#pragma unroll
            for (int c = 0; c < CH; c++) {
                rE[c][KW-1] = g_bufA[(0 * CH + c) * VOLP + base];  // xz-conv'd Cn
                rD[c][KW-1] = g_bufA[(1 * CH + c) * VOLP + base];  // xz-conv'd Cn²
            }
        } else {
#pragma unroll
            for (int c = 0; c < CH; c++) { rE[c][KW-1] = 0.f; rD[c][KW-1] = 0.f; }
        }

        if (k >= 6) {
            int y = s - 3;
            int iu = zxu + y * XD;
            int ip = zxp + y * XP;
            float Iv = I[iu];
            float a[CH];
#pragma unroll
            for (int c = 0; c < CH; c++) {
                float E = 0.f, D = 0.f;
#pragma unroll
                for (int t = 0; t < KW; t++) {
                    float w = swl[c][t];
                    E += w * rE[c][t]; D += w * rD[c][t];
                }
                float cones = slxz[c] * g_slif[c][y];
                float Lif = D - 2.f * Iv * E + Iv * Iv * cones;
                float q = sqxz[c] * g_sq[c][y] - 2.f * g_bufB[(2 * CH + c) * VOLP + ip];
                a[c] = (o[c * VOL + iu] - mu * Lif - lam * q) * inv_eta;
            }
            float m = fmaxf(fmaxf(a[0], a[1]), fmaxf(a[2], a[3]));
            float e0 = expf(a[0] - m), e1 = expf(a[1] - m);
            float e2 = expf(a[2] - m), e3 = expf(a[3] - m);
            float inv = 1.f / (e0 + e1 + e2 + e3);
            dst[iu] = e0 * inv;
            dst[VOL + iu] = e1 * inv;
            dst[2 * VOL + iu] = e2 * inv;
            dst[3 * VOL + iu] = e3 * inv;
        }
    }
}

// ---------------- launch ----------------
extern "C" void kernel_launch(void* const* d_in, const int* in_sizes, int n_in,
                              void* d_out, int out_size) {
    const float* o      = (const float*)d_in[0];
    const float* I      = (const float*)d_in[1];
    const float* sigma2 = (const float*)d_in[2];
    const float* sigma3 = (const float*)d_in[3];
    const float* eta    = (const float*)d_in[4];
    const float* lam    = (const float*)d_in[5];
    const float* mu     = (const float*)d_in[6];
    float* out = (float*)d_out;

    const int Tpt = 256;
    const int Bpt = (VOL + Tpt - 1) / Tpt;

    k_setup<<<1, 32>>>(sigma2, sigma3);
    k_init<<<Bpt, Tpt>>>(o, eta);
    {
        long padtotal = (long)3 * CH * ZD * YD * 8;
        int zb = (int)((padtotal + 255) / 256);
        k_zeropad<<<zb, 256>>>();
    }

    dim3 blkV(16, 16);
    dim3 blkS(32, 8);
    dim3 grid1(3, 6, NSEG1 * CH);   // 1152
    dim3 grid2(3, 6, NSEG2 * CH);   // 864
    dim3 grid3(3, 6, NSEG3 * CH);   // 1152
    dim3 grid4(3, 12, NSEG4);       // 432

    const int NB_ITERS = 10;
    for (int it = 0; it < NB_ITERS; ++it) {
        q1<<<grid1, blkV>>>(I);
        q2<<<grid2, blkV>>>();
        q3<<<grid3, blkV>>>();
        q4<<<grid4, blkS>>>(o, I, eta, lam, mu, out, (it == NB_ITERS - 1) ? 1 : 0);
    }
}

// round 12
// speedup vs baseline: 1.4411x; 1.3083x over previous
#include <cuda_runtime.h>

// Problem dims
#define ZD 96
#define YD 96
#define XD 96
#define PL 9216
#define VOL 884736
#define CH 4
#define KW 7

// Padded x-layout for intermediates
#define XP 104
#define XOFF 4
#define PLP (YD * XP)
#define VOLP (ZD * PLP)

// Segment configs
#define SEG1 6
#define NSEG1 16
#define SEG2 8
#define NSEG2 12
#define SEG3 6
#define NSEG3 16
#define SEG4 8
#define NSEG4 12

// ---------------- persistent device scratch ----------------
__device__ float g_wlif[CH][KW];
__device__ float g_wq[CH][KW];
__device__ float g_slif[CH][ZD];
__device__ float g_sq[CH][ZD];
__device__ int   g_same;
__device__ float g_u[CH * VOL];
__device__ float g_bufA[3 * CH * VOLP];
__device__ float g_bufB[3 * CH * VOLP];

// ---------------- zero the x-pad halos ----------------
__global__ void k_zeropad() {
    long nrows = (long)3 * CH * ZD * YD;
    long idx = (long)blockIdx.x * blockDim.x + threadIdx.x;
    long total = nrows * 8;
    if (idx >= total) return;
    long row = idx >> 3;
    int p = (int)(idx & 7);
    int xo = (p < 4) ? p : (XOFF + XD + p - 4);
    g_bufA[row * XP + xo] = 0.f;
    g_bufB[row * XP + xo] = 0.f;
}

// ---------------- setup ----------------
__global__ void k_setup(const float* __restrict__ sigma2,
                        const float* __restrict__ sigma3) {
    int c = threadIdx.x;
    if (c == 0) {
        int s = 1;
        for (int k = 0; k < CH; k++) s &= (sigma2[k] == sigma3[k]);
        g_same = s;
    }
    if (c < CH) {
        float s2 = sigma2[c], s3 = sigma3[c];
        float w2[KW], w3[KW];
        float sum2 = 0.f, sum3 = 0.f;
        for (int t = 0; t < KW; t++) {
            float d = (float)(t - 3);
            w2[t] = expf(-d * d / (2.f * s2 * s2)); sum2 += w2[t];
            w3[t] = expf(-d * d / (2.f * s3 * s3)); sum3 += w3[t];
        }
        for (int t = 0; t < KW; t++) {
            g_wq[c][t]   = w2[t] / sum2;
            g_wlif[c][t] = w3[t] / sum3;
        }
        for (int p = 0; p < ZD; p++) {
            float sl = 0.f, sq = 0.f;
            for (int t = 0; t < KW; t++) {
                int q = p + t - 3;
                if (q >= 0 && q < ZD) { sl += g_wlif[c][t]; sq += g_wq[c][t]; }
            }
            g_slif[c][p] = sl;
            g_sq[c][p]   = sq;
        }
    }
}

// ---------------- u0 = softmax(o / eta) ----------------
__global__ void k_init(const float* __restrict__ o,
                       const float* __restrict__ eta_p) {
    int i = blockIdx.x * blockDim.x + threadIdx.x;
    if (i >= VOL) return;
    float inv_eta = 1.f / eta_p[0];
    float a0 = o[i] * inv_eta;
    float a1 = o[VOL + i] * inv_eta;
    float a2 = o[2 * VOL + i] * inv_eta;
    float a3 = o[3 * VOL + i] * inv_eta;
    float m = fmaxf(fmaxf(a0, a1), fmaxf(a2, a3));
    float e0 = expf(a0 - m), e1 = expf(a1 - m), e2 = expf(a2 - m), e3 = expf(a3 - m);
    float inv = 1.f / (e0 + e1 + e2 + e3);
    g_u[i] = e0 * inv;
    g_u[VOL + i] = e1 * inv;
    g_u[2 * VOL + i] = e2 * inv;
    g_u[3 * VOL + i] = e3 * inv;
}

__device__ __forceinline__ void f2fma(float w, float2 v, float2& acc) {
    acc.x += w * v.x; acc.y += w * v.y;
}

// ============ q1: z-ring conv of {u*I, u} — float2 (exact R8) ============
template <bool SAME>
__device__ __forceinline__ void q1_body(const float* __restrict__ I,
                                        int c, int zs, int xy, int oxy) {
    float wl[KW], wq[KW];
#pragma unroll
    for (int t = 0; t < KW; t++) { wl[t] = g_wlif[c][t]; if (!SAME) wq[t] = g_wq[c][t]; }

    const float* uC = g_u + c * VOL;
    float2 rI[KW], rU[KW];
#pragma unroll
    for (int t = 0; t < KW; t++) { rI[t] = make_float2(0.f, 0.f); rU[t] = rI[t]; }

#pragma unroll
    for (int k = 0; k < SEG1 + 6; ++k) {
        const int s = zs - 3 + k;
#pragma unroll
        for (int t = 0; t < KW - 1; t++) { rI[t] = rI[t + 1]; rU[t] = rU[t + 1]; }
        float2 uv = make_float2(0.f, 0.f), Iv = uv;
        if (s >= 0 && s < ZD) {
            int gi = s * PL + xy;
            uv = *reinterpret_cast<const float2*>(uC + gi);
            Iv = *reinterpret_cast<const float2*>(I + gi);
        }
        rU[KW - 1] = uv;
        rI[KW - 1] = make_float2(uv.x * Iv.x, uv.y * Iv.y);
        if (k >= 6) {
            int z = s - 3;
            float2 a0 = make_float2(0.f, 0.f), a1 = a0;
#pragma unroll
            for (int t = 0; t < KW; t++) { f2fma(wl[t], rI[t], a0); f2fma(wl[t], rU[t], a1); }
            int oidx = z * PLP + oxy;
            *reinterpret_cast<float2*>(g_bufA + (0 * CH + c) * VOLP + oidx) = a0;
            *reinterpret_cast<float2*>(g_bufA + (1 * CH + c) * VOLP + oidx) = a1;
            if (!SAME) {
                float2 a2 = make_float2(0.f, 0.f);
#pragma unroll
                for (int t = 0; t < KW; t++) f2fma(wq[t], rU[t], a2);
                *reinterpret_cast<float2*>(g_bufA + (2 * CH + c) * VOLP + oidx) = a2;
            }
        }
    }
}

__global__ __launch_bounds__(256) void q1(const float* __restrict__ I) {
    const int x2 = blockIdx.x * 32 + threadIdx.x * 2;
    const int y  = blockIdx.y * 16 + threadIdx.y;
    const int bz = blockIdx.z;
    const int c  = bz / NSEG1;
    const int zs = (bz - c * NSEG1) * SEG1;
    const int xy  = y * XD + x2;
    const int oxy = y * XP + x2 + XOFF;
    if (g_same) q1_body<true>(I, c, zs, xy, oxy);
    else        q1_body<false>(I, c, zs, xy, oxy);
}

// x-tap pair: 5 aligned float2 loads
__device__ __forceinline__ float2 xtap_pair(const float* __restrict__ b, int bidx,
                                            const float* __restrict__ w) {
    float f[10];
    const float2* p = reinterpret_cast<const float2*>(b + bidx - 4);
#pragma unroll
    for (int j = 0; j < 5; j++) { float2 v = p[j]; f[2 * j] = v.x; f[2 * j + 1] = v.y; }
    float2 r = make_float2(0.f, 0.f);
#pragma unroll
    for (int t = 0; t < KW; t++) { r.x += w[t] * f[t + 1]; r.y += w[t] * f[t + 2]; }
    return r;
}

// x-tap pair + squared variant: one window, both conv(f) and conv(f^2)
__device__ __forceinline__ void xtap_pair_sq(const float* __restrict__ b, int bidx,
                                             const float* __restrict__ w,
                                             float2& rv, float2& rs) {
    float f[10];
    const float2* p = reinterpret_cast<const float2*>(b + bidx - 4);
#pragma unroll
    for (int j = 0; j < 5; j++) { float2 v = p[j]; f[2 * j] = v.x; f[2 * j + 1] = v.y; }
    rv = make_float2(0.f, 0.f); rs = rv;
#pragma unroll
    for (int t = 0; t < KW; t++) {
        float a = f[t + 1], bb = f[t + 2];
        rv.x += w[t] * a;        rv.y += w[t] * bb;
        rs.x += w[t] * (a * a);  rs.y += w[t] * (bb * bb);
    }
}

// ============ q2: y-ring + x-tap pairs -> Cn, C2q (Cn^2 recomputed later) ============
template <bool SAME>
__device__ __forceinline__ void q2_body(int c, int ys, int zx) {
    float wl[KW], wq[KW];
#pragma unroll
    for (int t = 0; t < KW; t++) { wl[t] = g_wlif[c][t]; if (!SAME) wq[t] = g_wq[c][t]; }

    const float* b0 = g_bufA + (0 * CH + c) * VOLP;
    const float* b1 = g_bufA + (1 * CH + c) * VOLP;
    const float* b2 = g_bufA + (2 * CH + c) * VOLP;

    float2 r0[KW], r1[KW], r2[KW];
#pragma unroll
    for (int t = 0; t < KW; t++) {
        r0[t] = make_float2(0.f, 0.f); r1[t] = r0[t];
        if (!SAME) r2[t] = r0[t];
    }

#pragma unroll
    for (int k = 0; k < SEG2 + 6; ++k) {
        const int s = ys - 3 + k;
#pragma unroll
        for (int t = 0; t < KW - 1; t++) {
            r0[t] = r0[t+1]; r1[t] = r1[t+1];
            if (!SAME) r2[t] = r2[t+1];
        }
        float2 v0 = make_float2(0.f, 0.f), v1 = v0, v2 = v0;
        if (s >= 0 && s < YD) {
            int base = zx + s * XP;
            v0 = xtap_pair(b0, base, wl);
            v1 = xtap_pair(b1, base, wl);
            if (!SAME) v2 = xtap_pair(b2, base, wq);
        }
        r0[KW-1] = v0; r1[KW-1] = v1;
        if (!SAME) r2[KW-1] = v2;
        if (k >= 6) {
            int y = s - 3;
            int oidx = zx + y * XP;
            float2 C1 = make_float2(0.f, 0.f), C2 = C1;
#pragma unroll
            for (int t = 0; t < KW; t++) { f2fma(wl[t], r0[t], C1); f2fma(wl[t], r1[t], C2); }
            float2 C2q;
            if (!SAME) {
                C2q = make_float2(0.f, 0.f);
#pragma unroll
                for (int t = 0; t < KW; t++) f2fma(wq[t], r2[t], C2q);
            } else {
                C2q = C2;
            }
            float2 Cn = make_float2((C1.x + 1e-6f) / (C2.x + 1e-6f),
                                    (C1.y + 1e-6f) / (C2.y + 1e-6f));
            *reinterpret_cast<float2*>(g_bufB + (0 * CH + c) * VOLP + oidx) = Cn;
            *reinterpret_cast<float2*>(g_bufB + (2 * CH + c) * VOLP + oidx) = C2q;
        }
    }
}

__global__ __launch_bounds__(256) void q2() {
    const int x2 = blockIdx.x * 32 + threadIdx.x * 2;
    const int z  = blockIdx.y * 16 + threadIdx.y;
    const int bz = blockIdx.z;
    const int c  = bz / NSEG2;
    const int ys = (bz - c * NSEG2) * SEG2;
    const int zx = z * PLP + x2 + XOFF;
    if (g_same) q2_body<true>(c, ys, zx);
    else        q2_body<false>(c, ys, zx);
}

// ============ q3: z-ring + x-taps of Cn (square on the fly) -> xz-conv'd (E,D) ============
__global__ __launch_bounds__(256) void q3() {
    const int x2 = blockIdx.x * 32 + threadIdx.x * 2;
    const int y  = blockIdx.y * 16 + threadIdx.y;
    const int bz = blockIdx.z;
    const int c  = bz / NSEG3;
    const int zs = (bz - c * NSEG3) * SEG3;
    const int xy = y * XP + x2 + XOFF;

    float wl[KW];
#pragma unroll
    for (int t = 0; t < KW; t++) wl[t] = g_wlif[c][t];

    const float* b0 = g_bufB + (0 * CH + c) * VOLP;   // Cn only

    float2 rE[KW], rD[KW];
#pragma unroll
    for (int t = 0; t < KW; t++) { rE[t] = make_float2(0.f, 0.f); rD[t] = rE[t]; }

#pragma unroll
    for (int k = 0; k < SEG3 + 6; ++k) {
        const int s = zs - 3 + k;
#pragma unroll
        for (int t = 0; t < KW - 1; t++) { rE[t] = rE[t+1]; rD[t] = rD[t+1]; }
        float2 vE = make_float2(0.f, 0.f), vD = vE;
        if (s >= 0 && s < ZD) {
            int gi = s * PLP + xy;
            xtap_pair_sq(b0, gi, wl, vE, vD);   // conv(Cn) and conv(Cn^2) from one window
        }
        rE[KW-1] = vE; rD[KW-1] = vD;
        if (k >= 6) {
            int z = s - 3;
            float2 a0 = make_float2(0.f, 0.f), a1 = a0;
#pragma unroll
            for (int t = 0; t < KW; t++) { f2fma(wl[t], rE[t], a0); f2fma(wl[t], rD[t], a1); }
            int oidx = z * PLP + xy;
            *reinterpret_cast<float2*>(g_bufA + (0 * CH + c) * VOLP + oidx) = a0;   // wx∘wz∘Cn
            *reinterpret_cast<float2*>(g_bufA + (1 * CH + c) * VOLP + oidx) = a1;   // wx∘wz∘Cn²
        }
    }
}

// ============ q4: y-ring (plain loads), ALL channels, Lif + q + softmax ============
__global__ __launch_bounds__(256) void q4(const float* __restrict__ o,
                                          const float* __restrict__ I,
                                          const float* __restrict__ eta_p,
                                          const float* __restrict__ lam_p,
                                          const float* __restrict__ mu_p,
                                          float* __restrict__ out,
                                          int write_ext) {
    const int x = blockIdx.x * 32 + threadIdx.x;
    const int z = blockIdx.y * 8 + threadIdx.y;
    const int ys = blockIdx.z * SEG4;
    const int zxp = z * PLP + x + XOFF;
    const int zxu = z * PL + x;

    __shared__ float swl[CH][KW];
    {
        int tid = threadIdx.y * 32 + threadIdx.x;
        if (tid < CH * KW) ((float*)swl)[tid] = ((const float*)g_wlif)[tid];
    }
    __syncthreads();

    const float lam = lam_p[0];
    const float mu  = mu_p[0];
    const float inv_eta = 1.f / eta_p[0];

    float slxz[CH], sqxz[CH];
#pragma unroll
    for (int c = 0; c < CH; c++) {
        slxz[c] = g_slif[c][x] * g_slif[c][z];
        sqxz[c] = g_sq[c][x] * g_sq[c][z];
    }

    float rE[CH][KW], rD[CH][KW];
#pragma unroll
    for (int c = 0; c < CH; c++)
#pragma unroll
        for (int t = 0; t < KW; t++) { rE[c][t] = 0.f; rD[c][t] = 0.f; }

    float* dst = write_ext ? out : g_u;

#pragma unroll
    for (int k = 0; k < SEG4 + 6; ++k) {
        const int s = ys - 3 + k;
#pragma unroll
        for (int c = 0; c < CH; c++)
#pragma unroll
            for (int t = 0; t < KW - 1; t++) { rE[c][t] = rE[c][t+1]; rD[c][t] = rD[c][t+1]; }

        if (s >= 0 && s < YD) {
            int base = zxp + s * XP;
#pragma unroll
            for (int c = 0; c < CH; c++) {
                rE[c][KW-1] = g_bufA[(0 * CH + c) * VOLP + base];  // xz-conv'd Cn
                rD[c][KW-1] = g_bufA[(1 * CH + c) * VOLP + base];  // xz-conv'd Cn²
            }
        } else {
#pragma unroll
            for (int c = 0; c < CH; c++) { rE[c][KW-1] = 0.f; rD[c][KW-1] = 0.f; }
        }

        if (k >= 6) {
            int y = s - 3;
            int iu = zxu + y * XD;
            int ip = zxp + y * XP;
            float Iv = I[iu];
            float a[CH];
#pragma unroll
            for (int c = 0; c < CH; c++) {
                float E = 0.f, D = 0.f;
#pragma unroll
                for (int t = 0; t < KW; t++) {
                    float w = swl[c][t];
                    E += w * rE[c][t]; D += w * rD[c][t];
                }
                float cones = slxz[c] * g_slif[c][y];
                float Lif = D - 2.f * Iv * E + Iv * Iv * cones;
                float q = sqxz[c] * g_sq[c][y] - 2.f * g_bufB[(2 * CH + c) * VOLP + ip];
                a[c] = (o[c * VOL + iu] - mu * Lif - lam * q) * inv_eta;
            }
            float m = fmaxf(fmaxf(a[0], a[1]), fmaxf(a[2], a[3]));
            float e0 = expf(a[0] - m), e1 = expf(a[1] - m);
            float e2 = expf(a[2] - m), e3 = expf(a[3] - m);
            float inv = 1.f / (e0 + e1 + e2 + e3);
            dst[iu] = e0 * inv;
            dst[VOL + iu] = e1 * inv;
            dst[2 * VOL + iu] = e2 * inv;
            dst[3 * VOL + iu] = e3 * inv;
        }
    }
}

// ---------------- launch ----------------
extern "C" void kernel_launch(void* const* d_in, const int* in_sizes, int n_in,
                              void* d_out, int out_size) {
    const float* o      = (const float*)d_in[0];
    const float* I      = (const float*)d_in[1];
    const float* sigma2 = (const float*)d_in[2];
    const float* sigma3 = (const float*)d_in[3];
    const float* eta    = (const float*)d_in[4];
    const float* lam    = (const float*)d_in[5];
    const float* mu     = (const float*)d_in[6];
    float* out = (float*)d_out;

    const int Tpt = 256;
    const int Bpt = (VOL + Tpt - 1) / Tpt;

    k_setup<<<1, 32>>>(sigma2, sigma3);
    k_init<<<Bpt, Tpt>>>(o, eta);
    {
        long padtotal = (long)3 * CH * ZD * YD * 8;
        int zb = (int)((padtotal + 255) / 256);
        k_zeropad<<<zb, 256>>>();
    }

    dim3 blkV(16, 16);
    dim3 blkS(32, 8);
    dim3 grid1(3, 6, NSEG1 * CH);   // 1152
    dim3 grid2(3, 6, NSEG2 * CH);   // 864
    dim3 grid3(3, 6, NSEG3 * CH);   // 1152
    dim3 grid4(3, 12, NSEG4);       // 432

    const int NB_ITERS = 10;
    for (int it = 0; it < NB_ITERS; ++it) {
        q1<<<grid1, blkV>>>(I);
        q2<<<grid2, blkV>>>();
        q3<<<grid3, blkV>>>();
        q4<<<grid4, blkS>>>(o, I, eta, lam, mu, out, (it == NB_ITERS - 1) ? 1 : 0);
    }
}

// round 13
// speedup vs baseline: 1.4680x; 1.0187x over previous
#include <cuda_runtime.h>

// Problem dims
#define ZD 96
#define YD 96
#define XD 96
#define PL 9216
#define VOL 884736
#define CH 4
#define KW 7

// Padded x-layout for intermediates
#define XP 104
#define XOFF 4
#define PLP (YD * XP)
#define VOLP (ZD * PLP)

// Segment configs (single-wave tuned: grid 576 @4/SM, 432 @3/SM)
#define SEG1 12
#define NSEG1 8
#define SEG2 12
#define NSEG2 8
#define SEG3 12
#define NSEG3 8
#define SEG4 8
#define NSEG4 12

// ---------------- persistent device scratch ----------------
__device__ float g_wlif[CH][KW];
__device__ float g_wq[CH][KW];
__device__ float g_slif[CH][ZD];
__device__ float g_sq[CH][ZD];
__device__ int   g_same;
__device__ float g_u[CH * VOL];
__device__ float g_bufA[3 * CH * VOLP];
__device__ float g_bufB[3 * CH * VOLP];

// ---------------- zero the x-pad halos ----------------
__global__ void k_zeropad() {
    long nrows = (long)3 * CH * ZD * YD;
    long idx = (long)blockIdx.x * blockDim.x + threadIdx.x;
    long total = nrows * 8;
    if (idx >= total) return;
    long row = idx >> 3;
    int p = (int)(idx & 7);
    int xo = (p < 4) ? p : (XOFF + XD + p - 4);
    g_bufA[row * XP + xo] = 0.f;
    g_bufB[row * XP + xo] = 0.f;
}

// ---------------- setup ----------------
__global__ void k_setup(const float* __restrict__ sigma2,
                        const float* __restrict__ sigma3) {
    int c = threadIdx.x;
    if (c == 0) {
        int s = 1;
        for (int k = 0; k < CH; k++) s &= (sigma2[k] == sigma3[k]);
        g_same = s;
    }
    if (c < CH) {
        float s2 = sigma2[c], s3 = sigma3[c];
        float w2[KW], w3[KW];
        float sum2 = 0.f, sum3 = 0.f;
        for (int t = 0; t < KW; t++) {
            float d = (float)(t - 3);
            w2[t] = expf(-d * d / (2.f * s2 * s2)); sum2 += w2[t];
            w3[t] = expf(-d * d / (2.f * s3 * s3)); sum3 += w3[t];
        }
        for (int t = 0; t < KW; t++) {
            g_wq[c][t]   = w2[t] / sum2;
            g_wlif[c][t] = w3[t] / sum3;
        }
        for (int p = 0; p < ZD; p++) {
            float sl = 0.f, sq = 0.f;
            for (int t = 0; t < KW; t++) {
                int q = p + t - 3;
                if (q >= 0 && q < ZD) { sl += g_wlif[c][t]; sq += g_wq[c][t]; }
            }
            g_slif[c][p] = sl;
            g_sq[c][p]   = sq;
        }
    }
}

// ---------------- u0 = softmax(o / eta) ----------------
__global__ void k_init(const float* __restrict__ o,
                       const float* __restrict__ eta_p) {
    int i = blockIdx.x * blockDim.x + threadIdx.x;
    if (i >= VOL) return;
    float inv_eta = 1.f / eta_p[0];
    float a0 = o[i] * inv_eta;
    float a1 = o[VOL + i] * inv_eta;
    float a2 = o[2 * VOL + i] * inv_eta;
    float a3 = o[3 * VOL + i] * inv_eta;
    float m = fmaxf(fmaxf(a0, a1), fmaxf(a2, a3));
    float e0 = expf(a0 - m), e1 = expf(a1 - m), e2 = expf(a2 - m), e3 = expf(a3 - m);
    float inv = 1.f / (e0 + e1 + e2 + e3);
    g_u[i] = e0 * inv;
    g_u[VOL + i] = e1 * inv;
    g_u[2 * VOL + i] = e2 * inv;
    g_u[3 * VOL + i] = e3 * inv;
}

__device__ __forceinline__ void f2fma(float w, float2 v, float2& acc) {
    acc.x += w * v.x; acc.y += w * v.y;
}

// ============ q1: z-ring conv of {u*I, u} — float2 ============
template <bool SAME>
__device__ __forceinline__ void q1_body(const float* __restrict__ I,
                                        int c, int zs, int xy, int oxy) {
    float wl[KW], wq[KW];
#pragma unroll
    for (int t = 0; t < KW; t++) { wl[t] = g_wlif[c][t]; if (!SAME) wq[t] = g_wq[c][t]; }

    const float* uC = g_u + c * VOL;
    float2 rI[KW], rU[KW];
#pragma unroll
    for (int t = 0; t < KW; t++) { rI[t] = make_float2(0.f, 0.f); rU[t] = rI[t]; }

#pragma unroll
    for (int k = 0; k < SEG1 + 6; ++k) {
        const int s = zs - 3 + k;
#pragma unroll
        for (int t = 0; t < KW - 1; t++) { rI[t] = rI[t + 1]; rU[t] = rU[t + 1]; }
        float2 uv = make_float2(0.f, 0.f), Iv = uv;
        if (s >= 0 && s < ZD) {
            int gi = s * PL + xy;
            uv = *reinterpret_cast<const float2*>(uC + gi);
            Iv = *reinterpret_cast<const float2*>(I + gi);
        }
        rU[KW - 1] = uv;
        rI[KW - 1] = make_float2(uv.x * Iv.x, uv.y * Iv.y);
        if (k >= 6) {
            int z = s - 3;
            float2 a0 = make_float2(0.f, 0.f), a1 = a0;
#pragma unroll
            for (int t = 0; t < KW; t++) { f2fma(wl[t], rI[t], a0); f2fma(wl[t], rU[t], a1); }
            int oidx = z * PLP + oxy;
            *reinterpret_cast<float2*>(g_bufA + (0 * CH + c) * VOLP + oidx) = a0;
            *reinterpret_cast<float2*>(g_bufA + (1 * CH + c) * VOLP + oidx) = a1;
            if (!SAME) {
                float2 a2 = make_float2(0.f, 0.f);
#pragma unroll
                for (int t = 0; t < KW; t++) f2fma(wq[t], rU[t], a2);
                *reinterpret_cast<float2*>(g_bufA + (2 * CH + c) * VOLP + oidx) = a2;
            }
        }
    }
}

__global__ __launch_bounds__(256) void q1(const float* __restrict__ I) {
    const int x2 = blockIdx.x * 32 + threadIdx.x * 2;
    const int y  = blockIdx.y * 16 + threadIdx.y;
    const int bz = blockIdx.z;
    const int c  = bz / NSEG1;
    const int zs = (bz - c * NSEG1) * SEG1;
    const int xy  = y * XD + x2;
    const int oxy = y * XP + x2 + XOFF;
    if (g_same) q1_body<true>(I, c, zs, xy, oxy);
    else        q1_body<false>(I, c, zs, xy, oxy);
}

// x-tap pair: 5 aligned float2 loads
__device__ __forceinline__ float2 xtap_pair(const float* __restrict__ b, int bidx,
                                            const float* __restrict__ w) {
    float f[10];
    const float2* p = reinterpret_cast<const float2*>(b + bidx - 4);
#pragma unroll
    for (int j = 0; j < 5; j++) { float2 v = p[j]; f[2 * j] = v.x; f[2 * j + 1] = v.y; }
    float2 r = make_float2(0.f, 0.f);
#pragma unroll
    for (int t = 0; t < KW; t++) { r.x += w[t] * f[t + 1]; r.y += w[t] * f[t + 2]; }
    return r;
}

// x-tap pair + squared variant: one window, both conv(f) and conv(f^2)
__device__ __forceinline__ void xtap_pair_sq(const float* __restrict__ b, int bidx,
                                             const float* __restrict__ w,
                                             float2& rv, float2& rs) {
    float f[10];
    const float2* p = reinterpret_cast<const float2*>(b + bidx - 4);
#pragma unroll
    for (int j = 0; j < 5; j++) { float2 v = p[j]; f[2 * j] = v.x; f[2 * j + 1] = v.y; }
    rv = make_float2(0.f, 0.f); rs = rv;
#pragma unroll
    for (int t = 0; t < KW; t++) {
        float a = f[t + 1], bb = f[t + 2];
        rv.x += w[t] * a;        rv.y += w[t] * bb;
        rs.x += w[t] * (a * a);  rs.y += w[t] * (bb * bb);
    }
}

// ============ q2: y-ring + x-tap pairs -> Cn, C2q ============
template <bool SAME>
__device__ __forceinline__ void q2_body(int c, int ys, int zx) {
    float wl[KW], wq[KW];
#pragma unroll
    for (int t = 0; t < KW; t++) { wl[t] = g_wlif[c][t]; if (!SAME) wq[t] = g_wq[c][t]; }

    const float* b0 = g_bufA + (0 * CH + c) * VOLP;
    const float* b1 = g_bufA + (1 * CH + c) * VOLP;
    const float* b2 = g_bufA + (2 * CH + c) * VOLP;

    float2 r0[KW], r1[KW], r2[KW];
#pragma unroll
    for (int t = 0; t < KW; t++) {
        r0[t] = make_float2(0.f, 0.f); r1[t] = r0[t];
        if (!SAME) r2[t] = r0[t];
    }

#pragma unroll
    for (int k = 0; k < SEG2 + 6; ++k) {
        const int s = ys - 3 + k;
#pragma unroll
        for (int t = 0; t < KW - 1; t++) {
            r0[t] = r0[t+1]; r1[t] = r1[t+1];
            if (!SAME) r2[t] = r2[t+1];
        }
        float2 v0 = make_float2(0.f, 0.f), v1 = v0, v2 = v0;
        if (s >= 0 && s < YD) {
            int base = zx + s * XP;
            v0 = xtap_pair(b0, base, wl);
            v1 = xtap_pair(b1, base, wl);
            if (!SAME) v2 = xtap_pair(b2, base, wq);
        }
        r0[KW-1] = v0; r1[KW-1] = v1;
        if (!SAME) r2[KW-1] = v2;
        if (k >= 6) {
            int y = s - 3;
            int oidx = zx + y * XP;
            float2 C1 = make_float2(0.f, 0.f), C2 = C1;
#pragma unroll
            for (int t = 0; t < KW; t++) { f2fma(wl[t], r0[t], C1); f2fma(wl[t], r1[t], C2); }
            float2 C2q;
            if (!SAME) {
                C2q = make_float2(0.f, 0.f);
#pragma unroll
                for (int t = 0; t < KW; t++) f2fma(wq[t], r2[t], C2q);
            } else {
                C2q = C2;
            }
            float2 Cn = make_float2((C1.x + 1e-6f) / (C2.x + 1e-6f),
                                    (C1.y + 1e-6f) / (C2.y + 1e-6f));
            *reinterpret_cast<float2*>(g_bufB + (0 * CH + c) * VOLP + oidx) = Cn;
            *reinterpret_cast<float2*>(g_bufB + (2 * CH + c) * VOLP + oidx) = C2q;
        }
    }
}

__global__ __launch_bounds__(256) void q2() {
    const int x2 = blockIdx.x * 32 + threadIdx.x * 2;
    const int z  = blockIdx.y * 16 + threadIdx.y;
    const int bz = blockIdx.z;
    const int c  = bz / NSEG2;
    const int ys = (bz - c * NSEG2) * SEG2;
    const int zx = z * PLP + x2 + XOFF;
    if (g_same) q2_body<true>(c, ys, zx);
    else        q2_body<false>(c, ys, zx);
}

// ============ q3: z-ring + x-taps of Cn (square on the fly) -> xz-conv'd (E,D) ============
__global__ __launch_bounds__(256) void q3() {
    const int x2 = blockIdx.x * 32 + threadIdx.x * 2;
    const int y  = blockIdx.y * 16 + threadIdx.y;
    const int bz = blockIdx.z;
    const int c  = bz / NSEG3;
    const int zs = (bz - c * NSEG3) * SEG3;
    const int xy = y * XP + x2 + XOFF;

    float wl[KW];
#pragma unroll
    for (int t = 0; t < KW; t++) wl[t] = g_wlif[c][t];

    const float* b0 = g_bufB + (0 * CH + c) * VOLP;   // Cn only

    float2 rE[KW], rD[KW];
#pragma unroll
    for (int t = 0; t < KW; t++) { rE[t] = make_float2(0.f, 0.f); rD[t] = rE[t]; }

#pragma unroll
    for (int k = 0; k < SEG3 + 6; ++k) {
        const int s = zs - 3 + k;
#pragma unroll
        for (int t = 0; t < KW - 1; t++) { rE[t] = rE[t+1]; rD[t] = rD[t+1]; }
        float2 vE = make_float2(0.f, 0.f), vD = vE;
        if (s >= 0 && s < ZD) {
            int gi = s * PLP + xy;
            xtap_pair_sq(b0, gi, wl, vE, vD);
        }
        rE[KW-1] = vE; rD[KW-1] = vD;
        if (k >= 6) {
            int z = s - 3;
            float2 a0 = make_float2(0.f, 0.f), a1 = a0;
#pragma unroll
            for (int t = 0; t < KW; t++) { f2fma(wl[t], rE[t], a0); f2fma(wl[t], rD[t], a1); }
            int oidx = z * PLP + xy;
            *reinterpret_cast<float2*>(g_bufA + (0 * CH + c) * VOLP + oidx) = a0;
            *reinterpret_cast<float2*>(g_bufA + (1 * CH + c) * VOLP + oidx) = a1;
        }
    }
}

// ============ q4: y-ring (plain loads), ALL channels, Lif + q + softmax ============
__global__ __launch_bounds__(256) void q4(const float* __restrict__ o,
                                          const float* __restrict__ I,
                                          const float* __restrict__ eta_p,
                                          const float* __restrict__ lam_p,
                                          const float* __restrict__ mu_p,
                                          float* __restrict__ out,
                                          int write_ext) {
    const int x = blockIdx.x * 32 + threadIdx.x;
    const int z = blockIdx.y * 8 + threadIdx.y;
    const int ys = blockIdx.z * SEG4;
    const int zxp = z * PLP + x + XOFF;
    const int zxu = z * PL + x;

    __shared__ float swl[CH][KW];
    {
        int tid = threadIdx.y * 32 + threadIdx.x;
        if (tid < CH * KW) ((float*)swl)[tid] = ((const float*)g_wlif)[tid];
    }
    __syncthreads();

    const float lam = lam_p[0];
    const float mu  = mu_p[0];
    const float inv_eta = 1.f / eta_p[0];

    float slxz[CH], sqxz[CH];
#pragma unroll
    for (int c = 0; c < CH; c++) {
        slxz[c] = g_slif[c][x] * g_slif[c][z];
        sqxz[c] = g_sq[c][x] * g_sq[c][z];
    }

    float rE[CH][KW], rD[CH][KW];
#pragma unroll
    for (int c = 0; c < CH; c++)
#pragma unroll
        for (int t = 0; t < KW; t++) { rE[c][t] = 0.f; rD[c][t] = 0.f; }

    float* dst = write_ext ? out : g_u;

#pragma unroll
    for (int k = 0; k < SEG4 + 6; ++k) {
        const int s = ys - 3 + k;
#pragma unroll
        for (int c = 0; c < CH; c++)
#pragma unroll
            for (int t = 0; t < KW - 1; t++) { rE[c][t] = rE[c][t+1]; rD[c][t] = rD[c][t+1]; }

        if (s >= 0 && s < YD) {
            int base = zxp + s * XP;
#pragma unroll
            for (int c = 0; c < CH; c++) {
                rE[c][KW-1] = g_bufA[(0 * CH + c) * VOLP + base];
                rD[c][KW-1] = g_bufA[(1 * CH + c) * VOLP + base];
            }
        } else {
#pragma unroll
            for (int c = 0; c < CH; c++) { rE[c][KW-1] = 0.f; rD[c][KW-1] = 0.f; }
        }

        if (k >= 6) {
            int y = s - 3;
            int iu = zxu + y * XD;
            int ip = zxp + y * XP;
            float Iv = I[iu];
            float a[CH];
#pragma unroll
            for (int c = 0; c < CH; c++) {
                float E = 0.f, D = 0.f;
#pragma unroll
                for (int t = 0; t < KW; t++) {
                    float w = swl[c][t];
                    E += w * rE[c][t]; D += w * rD[c][t];
                }
                float cones = slxz[c] * g_slif[c][y];
                float Lif = D - 2.f * Iv * E + Iv * Iv * cones;
                float q = sqxz[c] * g_sq[c][y] - 2.f * g_bufB[(2 * CH + c) * VOLP + ip];
                a[c] = (o[c * VOL + iu] - mu * Lif - lam * q) * inv_eta;
            }
            float m = fmaxf(fmaxf(a[0], a[1]), fmaxf(a[2], a[3]));
            float e0 = expf(a[0] - m), e1 = expf(a[1] - m);
            float e2 = expf(a[2] - m), e3 = expf(a[3] - m);
            float inv = 1.f / (e0 + e1 + e2 + e3);
            dst[iu] = e0 * inv;
            dst[VOL + iu] = e1 * inv;
            dst[2 * VOL + iu] = e2 * inv;
            dst[3 * VOL + iu] = e3 * inv;
        }
    }
}

// ---------------- launch ----------------
extern "C" void kernel_launch(void* const* d_in, const int* in_sizes, int n_in,
                              void* d_out, int out_size) {
    const float* o      = (const float*)d_in[0];
    const float* I      = (const float*)d_in[1];
    const float* sigma2 = (const float*)d_in[2];
    const float* sigma3 = (const float*)d_in[3];
    const float* eta    = (const float*)d_in[4];
    const float* lam    = (const float*)d_in[5];
    const float* mu     = (const float*)d_in[6];
    float* out = (float*)d_out;

    const int Tpt = 256;
    const int Bpt = (VOL + Tpt - 1) / Tpt;

    k_setup<<<1, 32>>>(sigma2, sigma3);
    k_init<<<Bpt, Tpt>>>(o, eta);
    {
        long padtotal = (long)3 * CH * ZD * YD * 8;
        int zb = (int)((padtotal + 255) / 256);
        k_zeropad<<<zb, 256>>>();
    }

    dim3 blkV(16, 16);
    dim3 blkS(32, 8);
    dim3 grid1(3, 6, NSEG1 * CH);   // 576 (single wave @4/SM)
    dim3 grid2(3, 6, NSEG2 * CH);   // 576
    dim3 grid3(3, 6, NSEG3 * CH);   // 576
    dim3 grid4(3, 12, NSEG4);       // 432 (single wave @3/SM)

    const int NB_ITERS = 10;
    for (int it = 0; it < NB_ITERS; ++it) {
        q1<<<grid1, blkV>>>(I);
        q2<<<grid2, blkV>>>();
        q3<<<grid3, blkV>>>();
        q4<<<grid4, blkS>>>(o, I, eta, lam, mu, out, (it == NB_ITERS - 1) ? 1 : 0);
    }
}